// round 6
// baseline (speedup 1.0000x reference)
#include <cuda_runtime.h>
#include <cuda_bf16.h>

#define N_NODES 100000
#define N_EDGES 800000
#define NF 81          // node features
#define NBOND 22       // bond features
#define OC 64          // out channels
#define CAP 64         // per-node edge bucket capacity (deg ~ Poisson(8); P(>64) ~ 1e-15)

typedef unsigned long long ull;

// Scratch (no allocations allowed)
__device__ float  g_Q[(size_t)N_NODES * OC];       // features @ w_n[0:81]  (25.6 MB)
__device__ float4 g_xyz[N_NODES];                  // packed coords (1.6 MB)
__device__ int    g_deg[N_NODES];                  // out-degree counters
__device__ int    g_bucket[(size_t)N_NODES * CAP]; // per-src edge lists (25.6 MB)

// ---- packed fp32x2 helpers (Blackwell FFMA2) --------------------------------
__device__ __forceinline__ void ffma2(ull& d, ull a, ull b) {
    asm("fma.rn.f32x2 %0, %1, %2, %0;" : "+l"(d) : "l"(a), "l"(b));
}
__device__ __forceinline__ ull pack2(float x) {
    ull r; asm("mov.b64 %0, {%1, %1};" : "=l"(r) : "f"(x)); return r;
}
__device__ __forceinline__ ull pack2f(float x, float y) {
    ull r; asm("mov.b64 %0, {%1, %2};" : "=l"(r) : "f"(x), "f"(y)); return r;
}
__device__ __forceinline__ float2 unpack2(ull v) {
    float2 r; asm("mov.b64 {%0, %1}, %2;" : "=f"(r.x), "=f"(r.y) : "l"(v)); return r;
}

// ---------------------------------------------------------------------------
// K1: fused node GEMM, BM=64 rows/block (63.5 KB smem -> 3 CTAs/SM).
// A = features [100k x 81], B = [w_s | w_n[0:81]] (81x128)
// out[n][c] = (A@w_s)[n][c], g_Q[n][c] = (A@w_n_node)[n][c]
// Epilogue: pack coords into g_xyz, zero g_deg.
// ---------------------------------------------------------------------------
#define BM 64
#define ASLD 68
#define K1_SMEM ((NF * ASLD + NF * 128) * 4)   // 63,504 B

__global__ __launch_bounds__(256) void k1_gemm(
    const float* __restrict__ feat,
    const float* __restrict__ w_s,
    const float* __restrict__ w_n,
    float* __restrict__ out)
{
    extern __shared__ float sm[];
    float* As = sm;                 // [NF][ASLD]  transposed A tile: As[k][r]
    float* Bs = sm + NF * ASLD;     // [NF][128]   c<64 -> w_s, c>=64 -> w_n

    const int tid = threadIdx.x;
    const int m0  = blockIdx.x * BM;

    for (int i = tid; i < BM * NF; i += 256) {
        int r = i / NF;
        int k = i - r * NF;
        int node = m0 + r;
        As[k * ASLD + r] = (node < N_NODES) ? feat[(size_t)node * NF + k] : 0.0f;
    }
    for (int i = tid; i < NF * OC; i += 256) {
        int k = i >> 6;
        int c = i & 63;
        Bs[k * 128 + c]      = w_s[i];
        Bs[k * 128 + 64 + c] = w_n[i];
    }
    __syncthreads();

    if (tid < BM) {
        int node = m0 + tid;
        if (node < N_NODES) {
            g_xyz[node] = make_float4(As[0 * ASLD + tid], As[1 * ASLD + tid],
                                      As[2 * ASLD + tid], 0.0f);
            g_deg[node] = 0;
        }
    }

    const int tx = tid & 15;   // 16 col-threads, 4 cols per 64-col half (in PAIRS)
    const int ty = tid >> 4;   // 16 row-threads, 4 rows each

    ull acc[4][4];
    #pragma unroll
    for (int i = 0; i < 4; i++)
        #pragma unroll
        for (int j = 0; j < 4; j++) acc[i][j] = 0ULL;

    const float* Ap = As + 4 * ty;
    const float* Bp = Bs + 4 * tx;

    #pragma unroll 3
    for (int k = 0; k < NF; k++) {
        float4 a0 = *(const float4*)(Ap + k * ASLD);
        ulonglong2 b01 = *(const ulonglong2*)(Bp + k * 128);        // w_s cols
        ulonglong2 b23 = *(const ulonglong2*)(Bp + k * 128 + 64);   // w_n cols
        ull av[4];
        av[0] = pack2(a0.x); av[1] = pack2(a0.y); av[2] = pack2(a0.z); av[3] = pack2(a0.w);
        #pragma unroll
        for (int i = 0; i < 4; i++) {
            ffma2(acc[i][0], av[i], b01.x);
            ffma2(acc[i][1], av[i], b01.y);
            ffma2(acc[i][2], av[i], b23.x);
            ffma2(acc[i][3], av[i], b23.y);
        }
    }

    #pragma unroll
    for (int i = 0; i < 4; i++) {
        int node = m0 + 4 * ty + i;
        if (node < N_NODES) {
            float2 p0 = unpack2(acc[i][0]);
            float2 p1 = unpack2(acc[i][1]);
            float2 p2 = unpack2(acc[i][2]);
            float2 p3 = unpack2(acc[i][3]);
            *(float4*)&out[(size_t)node * OC + 4 * tx] = make_float4(p0.x, p0.y, p1.x, p1.y);
            *(float4*)&g_Q[(size_t)node * OC + 4 * tx] = make_float4(p2.x, p2.y, p3.x, p3.y);
        }
    }
}

// ---------------------------------------------------------------------------
// Kh: bucket edges by src.  Spread scalar atomics only.
// ---------------------------------------------------------------------------
__global__ __launch_bounds__(256) void kh_bucket(const int* __restrict__ src)
{
    int e = blockIdx.x * 256 + threadIdx.x;
    if (e < N_EDGES) {
        int s = __ldg(&src[e]);
        int p = atomicAdd(&g_deg[s], 1);
        g_bucket[(size_t)s * CAP + p] = e;
    }
}

// ---------------------------------------------------------------------------
// K2': warp-per-node. For node n:
//   out[n] += sum_{e in bucket[n]} ( invd2_e * Q[dst_e] + bond_e @ Wb )
//           + sumw * (Q[n] - C[n])          (C[n] = xyz[n] @ w_n[0:3])
// All accumulation in registers; ONE non-atomic RMW per node. No atomics.
// ---------------------------------------------------------------------------
__global__ __launch_bounds__(256) void k2_nodes(
    const float* __restrict__ bond,
    const float* __restrict__ w_n,
    const int*   __restrict__ dst,
    float* __restrict__ out)
{
    const int lane = threadIdx.x & 31;
    const int n = blockIdx.x * 8 + (threadIdx.x >> 5);
    if (n >= N_NODES) return;
    const int c0 = 2 * lane;

    const int d = g_deg[n];        // lane-uniform broadcast load
    if (d == 0) return;            // out[n] already holds f@w_s from K1

    const float4 xs = __ldg(&g_xyz[n]);

    // bond-weight column pair for this lane, packed f32x2
    ull wb[NBOND];
    #pragma unroll
    for (int k = 0; k < NBOND; k++)
        wb[k] = *(const ull*)&w_n[(NF + k) * OC + c0];

    // prefetch edge list + dst per lane (deg <= 64; >32 is vanishingly rare)
    const int* bk = g_bucket + (size_t)n * CAP;
    int el0 = 0, dd0 = 0, el1 = 0, dd1 = 0;
    if (lane < d)      { el0 = __ldg(&bk[lane]);      dd0 = __ldg(&dst[el0]); }
    if (32 + lane < d) { el1 = __ldg(&bk[32 + lane]); dd1 = __ldg(&dst[el1]); }

    ull acc = 0ULL;
    float sumw = 0.0f;

    for (int i = 0; i < d; i++) {
        const int e  = (i < 32) ? __shfl_sync(0xffffffffu, el0, i)
                                : __shfl_sync(0xffffffffu, el1, i - 32);
        const int dd = (i < 32) ? __shfl_sync(0xffffffffu, dd0, i)
                                : __shfl_sync(0xffffffffu, dd1, i - 32);

        float4 xd = __ldg(&g_xyz[dd]);                  // broadcast
        float dx = xs.x - xd.x, dy = xs.y - xd.y, dz = xs.z - xd.z;
        float d2 = dx * dx + dy * dy + dz * dz;
        float w  = (d2 > 0.0f) ? (1.0f / d2) : 1e4f;
        sumw += w;

        // coalesced 256B row gather
        float2 q = *(const float2*)&g_Q[(size_t)dd * OC + c0];
        ffma2(acc, pack2(w), pack2f(q.x, q.y));

        float bval = (lane < NBOND) ? __ldg(&bond[(size_t)e * NBOND + lane]) : 0.0f;
        #pragma unroll
        for (int k = 0; k < NBOND; k++) {
            float bv = __shfl_sync(0xffffffffu, bval, k);
            ffma2(acc, pack2(bv), wb[k]);
        }
    }

    // tail: fold in sumw * (Q[n] - C[n]) and commit
    float2 qn = *(const float2*)&g_Q[(size_t)n * OC + c0];
    float cA = xs.x * __ldg(&w_n[0 * OC + c0])     + xs.y * __ldg(&w_n[1 * OC + c0])
             + xs.z * __ldg(&w_n[2 * OC + c0]);
    float cB = xs.x * __ldg(&w_n[0 * OC + c0 + 1]) + xs.y * __ldg(&w_n[1 * OC + c0 + 1])
             + xs.z * __ldg(&w_n[2 * OC + c0 + 1]);

    float2 a = unpack2(acc);
    float2 o = *(const float2*)&out[(size_t)n * OC + c0];
    o.x += a.x + sumw * (qn.x - cA);
    o.y += a.y + sumw * (qn.y - cB);
    *(float2*)&out[(size_t)n * OC + c0] = o;
}

// ---------------------------------------------------------------------------
extern "C" void kernel_launch(void* const* d_in, const int* in_sizes, int n_in,
                              void* d_out, int out_size)
{
    const float* feat = (const float*)d_in[0];
    const float* bond = (const float*)d_in[1];
    const float* w_s  = (const float*)d_in[2];
    const float* w_n  = (const float*)d_in[3];
    const int*   src  = (const int*)  d_in[4];
    const int*   dst  = (const int*)  d_in[5];
    float* out = (float*)d_out;

    (void)cudaFuncSetAttribute(k1_gemm, cudaFuncAttributeMaxDynamicSharedMemorySize, K1_SMEM);

    int grid1 = (N_NODES + BM - 1) / BM;                 // 1563
    k1_gemm<<<grid1, 256, K1_SMEM>>>(feat, w_s, w_n, out);

    kh_bucket<<<(N_EDGES + 255) / 256, 256>>>(src);      // 3125 blocks

    k2_nodes<<<(N_NODES + 7) / 8, 256>>>(bond, w_n, dst, out);   // 12500 blocks
}

// round 9
// speedup vs baseline: 2.1358x; 2.1358x over previous
#include <cuda_runtime.h>
#include <cuda_bf16.h>

#define N_NODES 100000
#define N_EDGES 800000
#define NF 81          // node features
#define NBOND 22       // bond features
#define OC 64          // out channels
#define CAP 64         // per-node bucket cap (deg ~ Poisson(8); max over 100k ~ 30)

typedef unsigned long long ull;

// Scratch (no allocations allowed)
__device__ float  g_Q[(size_t)N_NODES * OC];       // features @ w_n[0:81]  (25.6 MB)
__device__ float4 g_xyz[N_NODES];                  // packed coords (1.6 MB)
__device__ int    g_deg[N_NODES];                  // out-degree counters
__device__ int    g_bucket[(size_t)N_NODES * CAP]; // per-src edge lists (25.6 MB)

// ---- packed fp32x2 helpers (Blackwell FFMA2) --------------------------------
__device__ __forceinline__ void ffma2(ull& d, ull a, ull b) {
    asm("fma.rn.f32x2 %0, %1, %2, %0;" : "+l"(d) : "l"(a), "l"(b));
}
__device__ __forceinline__ ull pack2(float x) {
    ull r; asm("mov.b64 %0, {%1, %1};" : "=l"(r) : "f"(x)); return r;
}
__device__ __forceinline__ ull pack2f(float x, float y) {
    ull r; asm("mov.b64 %0, {%1, %2};" : "=l"(r) : "f"(x), "f"(y)); return r;
}
__device__ __forceinline__ float2 unpack2(ull v) {
    float2 r; asm("mov.b64 {%0, %1}, %2;" : "=f"(r.x), "=f"(r.y) : "l"(v)); return r;
}

// ---------------------------------------------------------------------------
// K1: fused node GEMM. BM=128 rows/block, 256 threads, 8 rows x 8 cols/thread.
// A tile row-major in smem (coalesced fill, broadcast scalar reads).
// out[n] = feat@w_s, g_Q[n] = feat@w_n[0:81]. Epilogue: g_xyz pack, g_deg=0.
// ---------------------------------------------------------------------------
#define BM 128
#define ALD 84                                   // 81 padded
#define K1_SMEM ((BM * ALD + NF * 128) * 4)      // 43008 + 41472 = 84480 B

__global__ __launch_bounds__(256) void k1_gemm(
    const float* __restrict__ feat,
    const float* __restrict__ w_s,
    const float* __restrict__ w_n,
    float* __restrict__ out)
{
    extern __shared__ float sm[];
    float* As = sm;                 // [BM][ALD] row-major
    float* Bs = sm + BM * ALD;      // [NF][128]  c<64 -> w_s, c>=64 -> w_n

    const int tid = threadIdx.x;
    const int m0  = blockIdx.x * BM;

    // A fill: coalesced global reads, conflict-free row-major smem stores
    for (int i = tid; i < BM * NF; i += 256) {
        int r = i / NF;
        int k = i - r * NF;
        int node = m0 + r;
        As[r * ALD + k] = (node < N_NODES) ? feat[(size_t)node * NF + k] : 0.0f;
    }
    for (int i = tid; i < NF * OC; i += 256) {
        int k = i >> 6;
        int c = i & 63;
        Bs[k * 128 + c]      = w_s[i];
        Bs[k * 128 + 64 + c] = w_n[i];
    }
    __syncthreads();

    if (tid < BM) {
        int node = m0 + tid;
        if (node < N_NODES) {
            g_xyz[node] = make_float4(As[tid * ALD + 0], As[tid * ALD + 1],
                                      As[tid * ALD + 2], 0.0f);
            g_deg[node] = 0;
        }
    }

    const int tx = tid & 15;   // 16 col-threads: 2 col-pairs per 64-col half
    const int ty = tid >> 4;   // 16 row-threads: 8 rows each

    ull acc[8][4];
    #pragma unroll
    for (int i = 0; i < 8; i++)
        #pragma unroll
        for (int j = 0; j < 4; j++) acc[i][j] = 0ULL;

    const float* Ap = As + (8 * ty) * ALD;
    const float* Bp = Bs + 4 * tx;

    #pragma unroll 3
    for (int k = 0; k < NF; k++) {
        ulonglong2 b01 = *(const ulonglong2*)(Bp + k * 128);        // w_s cols
        ulonglong2 b23 = *(const ulonglong2*)(Bp + k * 128 + 64);   // w_n cols
        #pragma unroll
        for (int i = 0; i < 8; i++) {
            ull av = pack2(Ap[i * ALD + k]);    // broadcast LDS.32 (16 tx share)
            ffma2(acc[i][0], av, b01.x);
            ffma2(acc[i][1], av, b01.y);
            ffma2(acc[i][2], av, b23.x);
            ffma2(acc[i][3], av, b23.y);
        }
    }

    #pragma unroll
    for (int i = 0; i < 8; i++) {
        int node = m0 + 8 * ty + i;
        if (node < N_NODES) {
            float2 p0 = unpack2(acc[i][0]);
            float2 p1 = unpack2(acc[i][1]);
            float2 p2 = unpack2(acc[i][2]);
            float2 p3 = unpack2(acc[i][3]);
            *(float4*)&out[(size_t)node * OC + 4 * tx] = make_float4(p0.x, p0.y, p1.x, p1.y);
            *(float4*)&g_Q[(size_t)node * OC + 4 * tx] = make_float4(p2.x, p2.y, p3.x, p3.y);
        }
    }
}

// ---------------------------------------------------------------------------
// Kh: bucket edges by src.  Spread scalar atomics only.
// ---------------------------------------------------------------------------
__global__ __launch_bounds__(256) void kh_bucket(const int* __restrict__ src)
{
    int e = blockIdx.x * 256 + threadIdx.x;
    if (e < N_EDGES) {
        int s = __ldg(&src[e]);
        int p = atomicAdd(&g_deg[s], 1);
        g_bucket[(size_t)s * CAP + p] = e;
    }
}

// ---------------------------------------------------------------------------
// K2: warp-per-node with bond-sum factorization.
//   out[n] += Sum_e invd2_e * Q[dst_e]             (per-edge: gather + 1 FFMA2)
//           + (Sum_e bond_e) @ Wb                  (per-NODE 22-step matvec)
//           + sumw * (Q[n] - C[n])                 (K3 absorbed)
// Per-edge w computed in PARALLEL per lane before the loop. No atomics.
// ---------------------------------------------------------------------------
__global__ __launch_bounds__(256) void k2_nodes(
    const float* __restrict__ bond,
    const float* __restrict__ w_n,
    const int*   __restrict__ dst,
    float* __restrict__ out)
{
    const int lane = threadIdx.x & 31;
    const int n = blockIdx.x * 8 + (threadIdx.x >> 5);
    if (n >= N_NODES) return;

    const int d = g_deg[n];
    if (d == 0) return;               // out[n] already = feat@w_s from K1
    const int c0 = 2 * lane;

    const float4 xs = __ldg(&g_xyz[n]);

    // lane-parallel edge prefetch + per-edge weight (slots lane, lane+32)
    const int* bk = g_bucket + (size_t)n * CAP;
    int   e0 = 0, e1 = 0, dd0 = 0, dd1 = 0;
    float w0 = 0.0f, w1 = 0.0f;
    if (lane < d) {
        e0 = __ldg(&bk[lane]);  dd0 = __ldg(&dst[e0]);
        float4 xd = __ldg(&g_xyz[dd0]);
        float dx = xs.x - xd.x, dy = xs.y - xd.y, dz = xs.z - xd.z;
        float d2 = dx * dx + dy * dy + dz * dz;
        w0 = (d2 > 0.0f) ? (1.0f / d2) : 1e4f;
    }
    if (32 + lane < d) {
        e1 = __ldg(&bk[32 + lane]);  dd1 = __ldg(&dst[e1]);
        float4 xd = __ldg(&g_xyz[dd1]);
        float dx = xs.x - xd.x, dy = xs.y - xd.y, dz = xs.z - xd.z;
        float d2 = dx * dx + dy * dy + dz * dz;
        w1 = (d2 > 0.0f) ? (1.0f / d2) : 1e4f;
    }

    // sumw via butterfly reduce
    float sumw = w0 + w1;
    #pragma unroll
    for (int off = 16; off > 0; off >>= 1)
        sumw += __shfl_xor_sync(0xffffffffu, sumw, off);

    // main loop: bond-sum (lanes 0..21) + weighted Q gather (all lanes), 2-way unrolled
    ull  acc = 0ULL, accB = 0ULL;
    float bsum = 0.0f;
    int i = 0;
    for (; i + 2 <= d; i += 2) {
        int   ea = __shfl_sync(0xffffffffu, (i     < 32) ? e0  : e1,  i      & 31);
        int   da = __shfl_sync(0xffffffffu, (i     < 32) ? dd0 : dd1, i      & 31);
        float wa = __shfl_sync(0xffffffffu, (i     < 32) ? w0  : w1,  i      & 31);
        int   eb = __shfl_sync(0xffffffffu, ((i+1) < 32) ? e0  : e1, (i + 1) & 31);
        int   db = __shfl_sync(0xffffffffu, ((i+1) < 32) ? dd0 : dd1,(i + 1) & 31);
        float wb_= __shfl_sync(0xffffffffu, ((i+1) < 32) ? w0  : w1, (i + 1) & 31);

        float2 qa = *(const float2*)&g_Q[(size_t)da * OC + c0];
        float2 qb = *(const float2*)&g_Q[(size_t)db * OC + c0];
        if (lane < NBOND) {
            bsum += __ldg(&bond[(size_t)ea * NBOND + lane]);
            bsum += __ldg(&bond[(size_t)eb * NBOND + lane]);
        }
        ffma2(acc,  pack2(wa),  pack2f(qa.x, qa.y));
        ffma2(accB, pack2(wb_), pack2f(qb.x, qb.y));
    }
    if (i < d) {
        int   ea = __shfl_sync(0xffffffffu, (i < 32) ? e0  : e1,  i & 31);
        int   da = __shfl_sync(0xffffffffu, (i < 32) ? dd0 : dd1, i & 31);
        float wa = __shfl_sync(0xffffffffu, (i < 32) ? w0  : w1,  i & 31);
        float2 qa = *(const float2*)&g_Q[(size_t)da * OC + c0];
        if (lane < NBOND) bsum += __ldg(&bond[(size_t)ea * NBOND + lane]);
        ffma2(acc, pack2(wa), pack2f(qa.x, qa.y));
    }
    asm("add.rn.f32x2 %0, %0, %1;" : "+l"(acc) : "l"(accB));

    // per-node bond matvec: 22 shfl + 22 FFMA2 (ONCE per node, not per edge)
    #pragma unroll
    for (int k = 0; k < NBOND; k++) {
        float bv = __shfl_sync(0xffffffffu, bsum, k);
        ull wbk = *(const ull*)&w_n[(NF + k) * OC + c0];
        ffma2(acc, pack2(bv), wbk);
    }

    // tail: + sumw * (Q[n] - C[n]);  C[n] = xyz @ w_n[0:3]
    float2 qn = *(const float2*)&g_Q[(size_t)n * OC + c0];
    float cA = xs.x * __ldg(&w_n[0 * OC + c0])     + xs.y * __ldg(&w_n[1 * OC + c0])
             + xs.z * __ldg(&w_n[2 * OC + c0]);
    float cB = xs.x * __ldg(&w_n[0 * OC + c0 + 1]) + xs.y * __ldg(&w_n[1 * OC + c0 + 1])
             + xs.z * __ldg(&w_n[2 * OC + c0 + 1]);

    float2 a = unpack2(acc);
    float2 o = *(const float2*)&out[(size_t)n * OC + c0];
    o.x += a.x + sumw * (qn.x - cA);
    o.y += a.y + sumw * (qn.y - cB);
    *(float2*)&out[(size_t)n * OC + c0] = o;
}

// ---------------------------------------------------------------------------
extern "C" void kernel_launch(void* const* d_in, const int* in_sizes, int n_in,
                              void* d_out, int out_size)
{
    const float* feat = (const float*)d_in[0];
    const float* bond = (const float*)d_in[1];
    const float* w_s  = (const float*)d_in[2];
    const float* w_n  = (const float*)d_in[3];
    const int*   src  = (const int*)  d_in[4];
    const int*   dst  = (const int*)  d_in[5];
    float* out = (float*)d_out;

    (void)cudaFuncSetAttribute(k1_gemm, cudaFuncAttributeMaxDynamicSharedMemorySize, K1_SMEM);

    int grid1 = (N_NODES + BM - 1) / BM;                 // 782
    k1_gemm<<<grid1, 256, K1_SMEM>>>(feat, w_s, w_n, out);

    kh_bucket<<<(N_EDGES + 255) / 256, 256>>>(src);      // 3125 blocks

    k2_nodes<<<(N_NODES + 7) / 8, 256>>>(bond, w_n, dst, out);   // 12500 blocks
}

// round 12
// speedup vs baseline: 2.5245x; 1.1820x over previous
#include <cuda_runtime.h>
#include <cuda_bf16.h>

#define N_NODES 100000
#define N_EDGES 800000
#define NF 81          // node features
#define NBOND 22       // bond features
#define OC 64          // out channels
#define CAP 64         // per-node bucket cap (deg ~ Poisson(8); max over 100k ~ 30)

typedef unsigned long long ull;

// Scratch (no allocations allowed)
__device__ float  g_Q[(size_t)N_NODES * OC];       // features @ w_n[0:81]  (25.6 MB)
__device__ float4 g_xyz[N_NODES];                  // packed coords (1.6 MB)
__device__ int    g_deg[N_NODES];                  // out-degree counters
__device__ int    g_bucket[(size_t)N_NODES * CAP]; // per-src edge lists (25.6 MB)

// ---- packed fp32x2 helpers (Blackwell FFMA2) --------------------------------
__device__ __forceinline__ void ffma2(ull& d, ull a, ull b) {
    asm("fma.rn.f32x2 %0, %1, %2, %0;" : "+l"(d) : "l"(a), "l"(b));
}
__device__ __forceinline__ ull pack2(float x) {
    ull r; asm("mov.b64 %0, {%1, %1};" : "=l"(r) : "f"(x)); return r;
}
__device__ __forceinline__ ull pack2f(float x, float y) {
    ull r; asm("mov.b64 %0, {%1, %2};" : "=l"(r) : "f"(x), "f"(y)); return r;
}
__device__ __forceinline__ float2 unpack2(ull v) {
    float2 r; asm("mov.b64 {%0, %1}, %2;" : "=f"(r.x), "=f"(r.y) : "l"(v)); return r;
}
__device__ __forceinline__ ull pack_iw(int i, float w) {
    ull r; asm("mov.b64 %0, {%1, %2};" : "=l"(r) : "r"(i), "f"(w)); return r;
}
__device__ __forceinline__ void unpack_iw(ull v, int& i, float& w) {
    asm("mov.b64 {%0, %1}, %2;" : "=r"(i), "=f"(w) : "l"(v));
}

// ---------------------------------------------------------------------------
// K1: fused node GEMM, BM=64 rows/block (63.5 KB smem -> 3 CTAs/SM).
// (round-6 config: measured 58.0us)
// out[n][c] = (feat@w_s)[n][c], g_Q[n][c] = (feat@w_n[0:81])[n][c]
// Epilogue: pack coords into g_xyz, zero g_deg.
// ---------------------------------------------------------------------------
#define BM 64
#define ASLD 68
#define K1_SMEM ((NF * ASLD + NF * 128) * 4)   // 63,504 B

__global__ __launch_bounds__(256) void k1_gemm(
    const float* __restrict__ feat,
    const float* __restrict__ w_s,
    const float* __restrict__ w_n,
    float* __restrict__ out)
{
    extern __shared__ float sm[];
    float* As = sm;                 // [NF][ASLD]  transposed A tile: As[k][r]
    float* Bs = sm + NF * ASLD;     // [NF][128]   c<64 -> w_s, c>=64 -> w_n

    const int tid = threadIdx.x;
    const int m0  = blockIdx.x * BM;

    for (int i = tid; i < BM * NF; i += 256) {
        int r = i / NF;
        int k = i - r * NF;
        int node = m0 + r;
        As[k * ASLD + r] = (node < N_NODES) ? feat[(size_t)node * NF + k] : 0.0f;
    }
    for (int i = tid; i < NF * OC; i += 256) {
        int k = i >> 6;
        int c = i & 63;
        Bs[k * 128 + c]      = w_s[i];
        Bs[k * 128 + 64 + c] = w_n[i];
    }
    __syncthreads();

    if (tid < BM) {
        int node = m0 + tid;
        if (node < N_NODES) {
            g_xyz[node] = make_float4(As[0 * ASLD + tid], As[1 * ASLD + tid],
                                      As[2 * ASLD + tid], 0.0f);
            g_deg[node] = 0;
        }
    }

    const int tx = tid & 15;   // 16 col-threads, 4 cols per 64-col half (in PAIRS)
    const int ty = tid >> 4;   // 16 row-threads, 4 rows each

    ull acc[4][4];
    #pragma unroll
    for (int i = 0; i < 4; i++)
        #pragma unroll
        for (int j = 0; j < 4; j++) acc[i][j] = 0ULL;

    const float* Ap = As + 4 * ty;
    const float* Bp = Bs + 4 * tx;

    #pragma unroll 3
    for (int k = 0; k < NF; k++) {
        float4 a0 = *(const float4*)(Ap + k * ASLD);
        ulonglong2 b01 = *(const ulonglong2*)(Bp + k * 128);        // w_s cols
        ulonglong2 b23 = *(const ulonglong2*)(Bp + k * 128 + 64);   // w_n cols
        ull av[4];
        av[0] = pack2(a0.x); av[1] = pack2(a0.y); av[2] = pack2(a0.z); av[3] = pack2(a0.w);
        #pragma unroll
        for (int i = 0; i < 4; i++) {
            ffma2(acc[i][0], av[i], b01.x);
            ffma2(acc[i][1], av[i], b01.y);
            ffma2(acc[i][2], av[i], b23.x);
            ffma2(acc[i][3], av[i], b23.y);
        }
    }

    #pragma unroll
    for (int i = 0; i < 4; i++) {
        int node = m0 + 4 * ty + i;
        if (node < N_NODES) {
            float2 p0 = unpack2(acc[i][0]);
            float2 p1 = unpack2(acc[i][1]);
            float2 p2 = unpack2(acc[i][2]);
            float2 p3 = unpack2(acc[i][3]);
            *(float4*)&out[(size_t)node * OC + 4 * tx] = make_float4(p0.x, p0.y, p1.x, p1.y);
            *(float4*)&g_Q[(size_t)node * OC + 4 * tx] = make_float4(p2.x, p2.y, p3.x, p3.y);
        }
    }
}

// ---------------------------------------------------------------------------
// Kh: bucket edges by src.  Spread scalar atomics only.
// ---------------------------------------------------------------------------
__global__ __launch_bounds__(256) void kh_bucket(const int* __restrict__ src)
{
    int e = blockIdx.x * 256 + threadIdx.x;
    if (e < N_EDGES) {
        int s = __ldg(&src[e]);
        int p = atomicAdd(&g_deg[s], 1);
        g_bucket[(size_t)s * CAP + p] = e;
    }
}

// ---------------------------------------------------------------------------
// K2: warp-per-node, smem-staged edge metadata, MLP-4 gathers.
//   out[n] += Sum_e invd2_e * Q[dst_e]             (4 gathers in flight)
//           + (Sum_e bond_e) @ Wb                  (per-NODE 22-step matvec)
//           + sumw * (Q[n] - C[n])
// Phase A (lane-parallel): compute (e, dd, w) per slot, pad to mult of 4
// with w=0 / e=-1. Phase B: broadcast LDS reads, 4 independent LDGs/iter.
// No atomics, no __syncthreads (per-warp smem regions).
// ---------------------------------------------------------------------------
#define NPB 8   // nodes (warps) per block

__global__ __launch_bounds__(256) void k2_nodes(
    const float* __restrict__ bond,
    const float* __restrict__ w_n,
    const int*   __restrict__ dst,
    float* __restrict__ out)
{
    __shared__ int s_e[NPB][CAP];
    __shared__ ull s_dw[NPB][CAP];    // packed (dd:int, w:float)

    const int lane = threadIdx.x & 31;
    const int wid  = threadIdx.x >> 5;
    const int n = blockIdx.x * NPB + wid;
    if (n >= N_NODES) return;

    const int d = g_deg[n];
    if (d == 0) return;               // out[n] already = feat@w_s from K1
    const int d_pad = (d + 3) & ~3;
    const int c0 = 2 * lane;

    const float4 xs = __ldg(&g_xyz[n]);
    const int* bk = g_bucket + (size_t)n * CAP;

    // Phase A: lane-parallel metadata (slots lane, lane+32)
    float wacc = 0.0f;
    #pragma unroll
    for (int h = 0; h < 2; h++) {
        int slot = lane + 32 * h;
        if (slot < d_pad) {
            int e = -1, dd = 0;
            float w = 0.0f;
            if (slot < d) {
                e  = __ldg(&bk[slot]);
                dd = __ldg(&dst[e]);
                float4 xd = __ldg(&g_xyz[dd]);
                float dx = xs.x - xd.x, dy = xs.y - xd.y, dz = xs.z - xd.z;
                float d2 = dx * dx + dy * dy + dz * dz;
                w = (d2 > 0.0f) ? (1.0f / d2) : 1e4f;
                wacc += w;
            }
            s_e[wid][slot]  = e;
            s_dw[wid][slot] = pack_iw(dd, w);
        }
    }
    // sumw via butterfly reduce
    float sumw = wacc;
    #pragma unroll
    for (int off = 16; off > 0; off >>= 1)
        sumw += __shfl_xor_sync(0xffffffffu, sumw, off);
    __syncwarp();

    // Phase B: 4 edges per iteration, independent gathers
    ull acc = 0ULL, accB = 0ULL;
    float bsum = 0.0f;
    for (int i = 0; i < d_pad; i += 4) {
        int e0 = s_e[wid][i],     e1 = s_e[wid][i + 1];
        int e2 = s_e[wid][i + 2], e3 = s_e[wid][i + 3];
        int dd0, dd1, dd2, dd3;
        float w0, w1, w2, w3;
        unpack_iw(s_dw[wid][i],     dd0, w0);
        unpack_iw(s_dw[wid][i + 1], dd1, w1);
        unpack_iw(s_dw[wid][i + 2], dd2, w2);
        unpack_iw(s_dw[wid][i + 3], dd3, w3);

        // 4 independent 8B Q-row gathers (coalesced 256B lines)
        float2 q0 = *(const float2*)&g_Q[(size_t)dd0 * OC + c0];
        float2 q1 = *(const float2*)&g_Q[(size_t)dd1 * OC + c0];
        float2 q2 = *(const float2*)&g_Q[(size_t)dd2 * OC + c0];
        float2 q3 = *(const float2*)&g_Q[(size_t)dd3 * OC + c0];

        // predicated bond loads (lanes 0..21; pads e<0 skip)
        float b0 = (lane < NBOND && e0 >= 0) ? __ldg(&bond[(size_t)e0 * NBOND + lane]) : 0.0f;
        float b1 = (lane < NBOND && e1 >= 0) ? __ldg(&bond[(size_t)e1 * NBOND + lane]) : 0.0f;
        float b2 = (lane < NBOND && e2 >= 0) ? __ldg(&bond[(size_t)e2 * NBOND + lane]) : 0.0f;
        float b3 = (lane < NBOND && e3 >= 0) ? __ldg(&bond[(size_t)e3 * NBOND + lane]) : 0.0f;
        bsum += (b0 + b1) + (b2 + b3);

        ffma2(acc,  pack2(w0), pack2f(q0.x, q0.y));
        ffma2(accB, pack2(w1), pack2f(q1.x, q1.y));
        ffma2(acc,  pack2(w2), pack2f(q2.x, q2.y));
        ffma2(accB, pack2(w3), pack2f(q3.x, q3.y));
    }
    asm("add.rn.f32x2 %0, %0, %1;" : "+l"(acc) : "l"(accB));

    // per-node bond matvec: 22 shfl + 22 FFMA2 (once per node)
    #pragma unroll
    for (int k = 0; k < NBOND; k++) {
        float bv = __shfl_sync(0xffffffffu, bsum, k);
        ull wbk = *(const ull*)&w_n[(NF + k) * OC + c0];
        ffma2(acc, pack2(bv), wbk);
    }

    // tail: + sumw * (Q[n] - C[n]);  C[n] = xyz @ w_n[0:3]
    float2 qn = *(const float2*)&g_Q[(size_t)n * OC + c0];
    float cA = xs.x * __ldg(&w_n[0 * OC + c0])     + xs.y * __ldg(&w_n[1 * OC + c0])
             + xs.z * __ldg(&w_n[2 * OC + c0]);
    float cB = xs.x * __ldg(&w_n[0 * OC + c0 + 1]) + xs.y * __ldg(&w_n[1 * OC + c0 + 1])
             + xs.z * __ldg(&w_n[2 * OC + c0 + 1]);

    float2 a = unpack2(acc);
    float2 o = *(const float2*)&out[(size_t)n * OC + c0];
    o.x += a.x + sumw * (qn.x - cA);
    o.y += a.y + sumw * (qn.y - cB);
    *(float2*)&out[(size_t)n * OC + c0] = o;
}

// ---------------------------------------------------------------------------
extern "C" void kernel_launch(void* const* d_in, const int* in_sizes, int n_in,
                              void* d_out, int out_size)
{
    const float* feat = (const float*)d_in[0];
    const float* bond = (const float*)d_in[1];
    const float* w_s  = (const float*)d_in[2];
    const float* w_n  = (const float*)d_in[3];
    const int*   src  = (const int*)  d_in[4];
    const int*   dst  = (const int*)  d_in[5];
    float* out = (float*)d_out;

    (void)cudaFuncSetAttribute(k1_gemm, cudaFuncAttributeMaxDynamicSharedMemorySize, K1_SMEM);

    int grid1 = (N_NODES + BM - 1) / BM;                 // 1563
    k1_gemm<<<grid1, 256, K1_SMEM>>>(feat, w_s, w_n, out);

    kh_bucket<<<(N_EDGES + 255) / 256, 256>>>(src);      // 3125 blocks

    k2_nodes<<<(N_NODES + NPB - 1) / NPB, 256>>>(bond, w_n, dst, out);   // 12500 blocks
}

// round 15
// speedup vs baseline: 2.6099x; 1.0338x over previous
#include <cuda_runtime.h>
#include <cuda_bf16.h>

#define N_NODES 100000
#define N_EDGES 800000
#define NF 81          // node features
#define NBOND 22       // bond features
#define OC 64          // out channels
#define CAP 64         // per-node bucket cap (deg ~ Poisson(8); max over 100k ~ 30)

typedef unsigned long long ull;

// Scratch (no allocations allowed)
__device__ float  g_Q[(size_t)N_NODES * OC];       // features @ w_n[0:81]  (25.6 MB)
__device__ float4 g_xyz[N_NODES];                  // packed coords (1.6 MB)
__device__ int    g_deg[N_NODES];                  // out-degree counters
__device__ ull    g_bucket[(size_t)N_NODES * CAP]; // per-src (edge, dst) pairs (51.2 MB)

// ---- packed fp32x2 helpers (Blackwell FFMA2) --------------------------------
__device__ __forceinline__ void ffma2(ull& d, ull a, ull b) {
    asm("fma.rn.f32x2 %0, %1, %2, %0;" : "+l"(d) : "l"(a), "l"(b));
}
__device__ __forceinline__ ull pack2(float x) {
    ull r; asm("mov.b64 %0, {%1, %1};" : "=l"(r) : "f"(x)); return r;
}
__device__ __forceinline__ ull pack2f(float x, float y) {
    ull r; asm("mov.b64 %0, {%1, %2};" : "=l"(r) : "f"(x), "f"(y)); return r;
}
__device__ __forceinline__ float2 unpack2(ull v) {
    float2 r; asm("mov.b64 {%0, %1}, %2;" : "=f"(r.x), "=f"(r.y) : "l"(v)); return r;
}
__device__ __forceinline__ ull pack_iw(int i, float w) {
    ull r; asm("mov.b64 %0, {%1, %2};" : "=l"(r) : "r"(i), "f"(w)); return r;
}
__device__ __forceinline__ void unpack_iw(ull v, int& i, float& w) {
    asm("mov.b64 {%0, %1}, %2;" : "=r"(i), "=f"(w) : "l"(v));
}

// ---- cp.async helpers -------------------------------------------------------
__device__ __forceinline__ void cpa4(unsigned dst, const void* src, int ssz) {
    asm volatile("cp.async.ca.shared.global [%0], [%1], 4, %2;"
                 :: "r"(dst), "l"(src), "r"(ssz));
}
__device__ __forceinline__ void cpa16(unsigned dst, const void* src) {
    asm volatile("cp.async.ca.shared.global [%0], [%1], 16;"
                 :: "r"(dst), "l"(src));
}
__device__ __forceinline__ void cpa_commit() {
    asm volatile("cp.async.commit_group;");
}

// ---------------------------------------------------------------------------
// K1: fused node GEMM, BM=64 rows/block, cp.async double-buffered k-chunks.
// Chunk0 = k[0,41), chunk1 = k[41,81). Both chunk loads issued up front;
// compute(chunk0) overlaps chunk1's inflight cp.async.
// out[n] = feat@w_s, g_Q[n] = feat@w_n[0:81]. Epilogue: g_xyz pack, g_deg=0.
// ---------------------------------------------------------------------------
#define BM 64
#define ASLD 68
#define KC0 41
#define K1_SMEM ((NF * ASLD + NF * 128) * 4)   // 63,504 B -> 3 CTAs/SM

__global__ __launch_bounds__(256) void k1_gemm(
    const float* __restrict__ feat,
    const float* __restrict__ w_s,
    const float* __restrict__ w_n,
    float* __restrict__ out)
{
    extern __shared__ float sm[];
    float* As = sm;                 // [NF][ASLD] transposed A tile
    float* Bs = sm + NF * ASLD;     // [NF][128]  c<64 -> w_s, c>=64 -> w_n

    const int tid = threadIdx.x;
    const int m0  = blockIdx.x * BM;
    const unsigned As_s = (unsigned)__cvta_generic_to_shared(As);
    const unsigned Bs_s = (unsigned)__cvta_generic_to_shared(Bs);

    // issue both chunk loads via cp.async (group per chunk)
    #pragma unroll
    for (int c = 0; c < 2; c++) {
        const int k0 = c ? KC0 : 0;
        const int kc = c ? (NF - KC0) : KC0;
        // A: 4B ops, coalesced in k within a node row; OOB rows zero-filled
        for (int i = tid; i < BM * kc; i += 256) {
            int r  = i / kc;
            int kk = i - r * kc + k0;
            int node = m0 + r;
            const float* src = feat + (size_t)node * NF + kk;
            cpa4(As_s + (kk * ASLD + r) * 4, src, node < N_NODES ? 4 : 0);
        }
        // B: 16B ops; per k-row, 16 vec4 from w_s then 16 from w_n
        for (int i = tid; i < kc * 32; i += 256) {
            int k = (i >> 5) + k0;
            int g = i & 31;
            if (g < 16) cpa16(Bs_s + (k * 128 + g * 4) * 4,        w_s + k * OC + g * 4);
            else        cpa16(Bs_s + (k * 128 + 64 + (g-16)*4) * 4, w_n + k * OC + (g-16)*4);
        }
        cpa_commit();
    }

    asm volatile("cp.async.wait_group 1;");   // chunk0 complete
    __syncthreads();

    if (tid < BM) {
        int node = m0 + tid;
        if (node < N_NODES) {
            g_xyz[node] = make_float4(As[0 * ASLD + tid], As[1 * ASLD + tid],
                                      As[2 * ASLD + tid], 0.0f);
            g_deg[node] = 0;
        }
    }

    const int tx = tid & 15;   // 16 col-threads, 4 cols per 64-col half (PAIRS)
    const int ty = tid >> 4;   // 16 row-threads, 4 rows each

    ull acc[4][4];
    #pragma unroll
    for (int i = 0; i < 4; i++)
        #pragma unroll
        for (int j = 0; j < 4; j++) acc[i][j] = 0ULL;

    const float* Ap = As + 4 * ty;
    const float* Bp = Bs + 4 * tx;

    // compute chunk0 while chunk1 streams in
    #pragma unroll 4
    for (int k = 0; k < KC0; k++) {
        float4 a0 = *(const float4*)(Ap + k * ASLD);
        ulonglong2 b01 = *(const ulonglong2*)(Bp + k * 128);
        ulonglong2 b23 = *(const ulonglong2*)(Bp + k * 128 + 64);
        ull av[4];
        av[0] = pack2(a0.x); av[1] = pack2(a0.y); av[2] = pack2(a0.z); av[3] = pack2(a0.w);
        #pragma unroll
        for (int i = 0; i < 4; i++) {
            ffma2(acc[i][0], av[i], b01.x);
            ffma2(acc[i][1], av[i], b01.y);
            ffma2(acc[i][2], av[i], b23.x);
            ffma2(acc[i][3], av[i], b23.y);
        }
    }

    asm volatile("cp.async.wait_group 0;");   // chunk1 complete
    __syncthreads();

    #pragma unroll 4
    for (int k = KC0; k < NF; k++) {
        float4 a0 = *(const float4*)(Ap + k * ASLD);
        ulonglong2 b01 = *(const ulonglong2*)(Bp + k * 128);
        ulonglong2 b23 = *(const ulonglong2*)(Bp + k * 128 + 64);
        ull av[4];
        av[0] = pack2(a0.x); av[1] = pack2(a0.y); av[2] = pack2(a0.z); av[3] = pack2(a0.w);
        #pragma unroll
        for (int i = 0; i < 4; i++) {
            ffma2(acc[i][0], av[i], b01.x);
            ffma2(acc[i][1], av[i], b01.y);
            ffma2(acc[i][2], av[i], b23.x);
            ffma2(acc[i][3], av[i], b23.y);
        }
    }

    #pragma unroll
    for (int i = 0; i < 4; i++) {
        int node = m0 + 4 * ty + i;
        if (node < N_NODES) {
            float2 p0 = unpack2(acc[i][0]);
            float2 p1 = unpack2(acc[i][1]);
            float2 p2 = unpack2(acc[i][2]);
            float2 p3 = unpack2(acc[i][3]);
            *(float4*)&out[(size_t)node * OC + 4 * tx] = make_float4(p0.x, p0.y, p1.x, p1.y);
            *(float4*)&g_Q[(size_t)node * OC + 4 * tx] = make_float4(p2.x, p2.y, p3.x, p3.y);
        }
    }
}

// ---------------------------------------------------------------------------
// Kh: bucket edges by src, storing (edge, dst[edge]) packed — removes one
// level of the gather chain from K2 phase A. dst read here is coalesced.
// ---------------------------------------------------------------------------
__global__ __launch_bounds__(256) void kh_bucket(
    const int* __restrict__ src, const int* __restrict__ dst)
{
    int e = blockIdx.x * 256 + threadIdx.x;
    if (e < N_EDGES) {
        int s = __ldg(&src[e]);
        int d = __ldg(&dst[e]);
        int p = atomicAdd(&g_deg[s], 1);
        g_bucket[(size_t)s * CAP + p] = (ull)(unsigned)e | ((ull)(unsigned)d << 32);
    }
}

// ---------------------------------------------------------------------------
// K2: warp-per-node, smem-staged edge metadata, MLP-4 gathers.
//   out[n] += Sum_e invd2_e * Q[dst_e] + (Sum_e bond_e) @ Wb + sumw*(Q[n]-C[n])
// Phase A: 2-deep gather chain (bucket pair -> xyz). Phase B: 4 edges/iter.
// ---------------------------------------------------------------------------
#define NPB 8   // nodes (warps) per block

__global__ __launch_bounds__(256) void k2_nodes(
    const float* __restrict__ bond,
    const float* __restrict__ w_n,
    float* __restrict__ out)
{
    __shared__ int s_e[NPB][CAP];
    __shared__ ull s_dw[NPB][CAP];    // packed (dd:int, w:float)

    const int lane = threadIdx.x & 31;
    const int wid  = threadIdx.x >> 5;
    const int n = blockIdx.x * NPB + wid;
    if (n >= N_NODES) return;

    const int d = g_deg[n];
    if (d == 0) return;               // out[n] already = feat@w_s from K1
    const int d_pad = (d + 3) & ~3;
    const int c0 = 2 * lane;

    const float4 xs = __ldg(&g_xyz[n]);
    const ull* bk = g_bucket + (size_t)n * CAP;

    // Phase A: lane-parallel metadata (slots lane, lane+32); 2-deep LDG chain
    float wacc = 0.0f;
    #pragma unroll
    for (int h = 0; h < 2; h++) {
        int slot = lane + 32 * h;
        if (slot < d_pad) {
            int e = -1, dd = 0;
            float w = 0.0f;
            if (slot < d) {
                ull v = __ldg(&bk[slot]);
                e  = (int)(unsigned)(v & 0xffffffffu);
                dd = (int)(unsigned)(v >> 32);
                float4 xd = __ldg(&g_xyz[dd]);
                float dx = xs.x - xd.x, dy = xs.y - xd.y, dz = xs.z - xd.z;
                float d2 = dx * dx + dy * dy + dz * dz;
                w = (d2 > 0.0f) ? (1.0f / d2) : 1e4f;
                wacc += w;
            }
            s_e[wid][slot]  = e;
            s_dw[wid][slot] = pack_iw(dd, w);
        }
    }
    float sumw = wacc;
    #pragma unroll
    for (int off = 16; off > 0; off >>= 1)
        sumw += __shfl_xor_sync(0xffffffffu, sumw, off);
    __syncwarp();

    // Phase B: 4 edges per iteration, independent gathers
    ull acc = 0ULL, accB = 0ULL;
    float bsum = 0.0f;
    for (int i = 0; i < d_pad; i += 4) {
        int e0 = s_e[wid][i],     e1 = s_e[wid][i + 1];
        int e2 = s_e[wid][i + 2], e3 = s_e[wid][i + 3];
        int dd0, dd1, dd2, dd3;
        float w0, w1, w2, w3;
        unpack_iw(s_dw[wid][i],     dd0, w0);
        unpack_iw(s_dw[wid][i + 1], dd1, w1);
        unpack_iw(s_dw[wid][i + 2], dd2, w2);
        unpack_iw(s_dw[wid][i + 3], dd3, w3);

        float2 q0 = *(const float2*)&g_Q[(size_t)dd0 * OC + c0];
        float2 q1 = *(const float2*)&g_Q[(size_t)dd1 * OC + c0];
        float2 q2 = *(const float2*)&g_Q[(size_t)dd2 * OC + c0];
        float2 q3 = *(const float2*)&g_Q[(size_t)dd3 * OC + c0];

        float b0 = (lane < NBOND && e0 >= 0) ? __ldg(&bond[(size_t)e0 * NBOND + lane]) : 0.0f;
        float b1 = (lane < NBOND && e1 >= 0) ? __ldg(&bond[(size_t)e1 * NBOND + lane]) : 0.0f;
        float b2 = (lane < NBOND && e2 >= 0) ? __ldg(&bond[(size_t)e2 * NBOND + lane]) : 0.0f;
        float b3 = (lane < NBOND && e3 >= 0) ? __ldg(&bond[(size_t)e3 * NBOND + lane]) : 0.0f;
        bsum += (b0 + b1) + (b2 + b3);

        ffma2(acc,  pack2(w0), pack2f(q0.x, q0.y));
        ffma2(accB, pack2(w1), pack2f(q1.x, q1.y));
        ffma2(acc,  pack2(w2), pack2f(q2.x, q2.y));
        ffma2(accB, pack2(w3), pack2f(q3.x, q3.y));
    }
    asm("add.rn.f32x2 %0, %0, %1;" : "+l"(acc) : "l"(accB));

    // per-node bond matvec (once per node)
    #pragma unroll
    for (int k = 0; k < NBOND; k++) {
        float bv = __shfl_sync(0xffffffffu, bsum, k);
        ull wbk = *(const ull*)&w_n[(NF + k) * OC + c0];
        ffma2(acc, pack2(bv), wbk);
    }

    // tail: + sumw * (Q[n] - C[n]);  C[n] = xyz @ w_n[0:3]
    float2 qn = *(const float2*)&g_Q[(size_t)n * OC + c0];
    float cA = xs.x * __ldg(&w_n[0 * OC + c0])     + xs.y * __ldg(&w_n[1 * OC + c0])
             + xs.z * __ldg(&w_n[2 * OC + c0]);
    float cB = xs.x * __ldg(&w_n[0 * OC + c0 + 1]) + xs.y * __ldg(&w_n[1 * OC + c0 + 1])
             + xs.z * __ldg(&w_n[2 * OC + c0 + 1]);

    float2 a = unpack2(acc);
    float2 o = *(const float2*)&out[(size_t)n * OC + c0];
    o.x += a.x + sumw * (qn.x - cA);
    o.y += a.y + sumw * (qn.y - cB);
    *(float2*)&out[(size_t)n * OC + c0] = o;
}

// ---------------------------------------------------------------------------
extern "C" void kernel_launch(void* const* d_in, const int* in_sizes, int n_in,
                              void* d_out, int out_size)
{
    const float* feat = (const float*)d_in[0];
    const float* bond = (const float*)d_in[1];
    const float* w_s  = (const float*)d_in[2];
    const float* w_n  = (const float*)d_in[3];
    const int*   src  = (const int*)  d_in[4];
    const int*   dst  = (const int*)  d_in[5];
    float* out = (float*)d_out;

    (void)cudaFuncSetAttribute(k1_gemm, cudaFuncAttributeMaxDynamicSharedMemorySize, K1_SMEM);

    int grid1 = (N_NODES + BM - 1) / BM;                 // 1563
    k1_gemm<<<grid1, 256, K1_SMEM>>>(feat, w_s, w_n, out);

    kh_bucket<<<(N_EDGES + 255) / 256, 256>>>(src, dst); // 3125 blocks

    k2_nodes<<<(N_NODES + NPB - 1) / NPB, 256>>>(bond, w_n, out);   // 12500 blocks
}